// round 5
// baseline (speedup 1.0000x reference)
#include <cuda_runtime.h>

// Analytic collapse of the 16-qubit circuit (rounds 1-4):
//   theta = x @ W_in^T + b_in
//   e[b,k] = prod_{j<=k, (k-j)%4 in {0,1}} cos(theta[b,j])
//          = A_{k%4}(k) * A_{(k-1)%4}(k-1)  (residue-class prefix products)
//   out    = e @ W_out^T + b_out
// q_weights provably cannot affect the output (diagonal phases + permutations).
//
// R5: R4's lean inner (one barrier, register prefix chains, hoisted epilogue
// operands) in a one-row-per-CTA shell: grid 256 x block 128 -> 2 CTAs/SM
// co-resident, plain 4-warp BAR, 12 front LDG.128 per thread.

__global__ void __launch_bounds__(128) quantum_layer_kernel(
    const float4* __restrict__ x4,    // (256, 32) float4
    const float4* __restrict__ Wi4,   // (16, 32)  float4
    const float*  __restrict__ b_in,  // (16)
    const float4* __restrict__ Wo4,   // (128, 4)  float4
    const float*  __restrict__ b_out, // (128)
    float* __restrict__ out)          // (256, 128)
{
    __shared__ float cs[16];

    const int t  = threadIdx.x;
    const int b  = blockIdx.x;
    const int q  = t >> 3;            // 16 qubits, 8 lanes each
    const int e8 = t & 7;

    // ---- Hoist everything the epilogue needs: latency hides under the dot. ----
    const float4* wo = Wo4 + t * 4;
    const float4 w0 = wo[0], w1 = wo[1], w2 = wo[2], w3 = wo[3];
    const float  bo = b_out[t];
    const float  bq = b_in[q];

    // ---- theta[b,q]: 8 lanes x 16 elements (4x LDG.128 each). ----
    const float4* xp = x4  + b * 32 + e8 * 4;
    const float4* wp = Wi4 + q * 32 + e8 * 4;
    float4 xa = xp[0], wa = wp[0];
    float4 xb = xp[1], wb = wp[1];
    float4 xc = xp[2], wc = wp[2];
    float4 xd = xp[3], wd = wp[3];
    float p0 = xa.x*wa.x + xa.y*wa.y + xa.z*wa.z + xa.w*wa.w;
    float p1 = xb.x*wb.x + xb.y*wb.y + xb.z*wb.z + xb.w*wb.w;
    float p2 = xc.x*wc.x + xc.y*wc.y + xc.z*wc.z + xc.w*wc.w;
    float p3 = xd.x*wd.x + xd.y*wd.y + xd.z*wd.z + xd.w*wd.w;
    float p = (p0 + p1) + (p2 + p3);
    p += __shfl_xor_sync(0xffffffffu, p, 4);
    p += __shfl_xor_sync(0xffffffffu, p, 2);
    p += __shfl_xor_sync(0xffffffffu, p, 1);
    if (e8 == 0) cs[q] = __cosf(p + bq);   // MUFU; |theta| small, tol 1e-3
    __syncthreads();

    // ---- Per-thread residue-class prefix chains (depth ~4 FMUL per chain). ----
    float c[16];
    #pragma unroll
    for (int j = 0; j < 16; j += 4) {
        float4 v = *reinterpret_cast<const float4*>(&cs[j]);   // LDS.128 broadcast
        c[j] = v.x; c[j+1] = v.y; c[j+2] = v.z; c[j+3] = v.w;
    }
    float e[16];
    float A0, A1, A2, A3;
    A0 = c[0];          e[0]  = A0;
    A1 = c[1];          e[1]  = A1 * A0;
    A2 = c[2];          e[2]  = A2 * A1;
    A3 = c[3];          e[3]  = A3 * A2;
    A0 *= c[4];         e[4]  = A0 * A3;
    A1 *= c[5];         e[5]  = A1 * A0;
    A2 *= c[6];         e[6]  = A2 * A1;
    A3 *= c[7];         e[7]  = A3 * A2;
    A0 *= c[8];         e[8]  = A0 * A3;
    A1 *= c[9];         e[9]  = A1 * A0;
    A2 *= c[10];        e[10] = A2 * A1;
    A3 *= c[11];        e[11] = A3 * A2;
    A0 *= c[12];        e[12] = A0 * A3;
    A1 *= c[13];        e[13] = A1 * A0;
    A2 *= c[14];        e[14] = A2 * A1;
    A3 *= c[15];        e[15] = A3 * A2;

    // ---- out[b,t] = b_out[t] + sum_k e[k] * W_out[t,k]  (weights preloaded). ----
    float acc = bo;
    acc = fmaf(e[0],  w0.x, acc); acc = fmaf(e[1],  w0.y, acc);
    acc = fmaf(e[2],  w0.z, acc); acc = fmaf(e[3],  w0.w, acc);
    acc = fmaf(e[4],  w1.x, acc); acc = fmaf(e[5],  w1.y, acc);
    acc = fmaf(e[6],  w1.z, acc); acc = fmaf(e[7],  w1.w, acc);
    acc = fmaf(e[8],  w2.x, acc); acc = fmaf(e[9],  w2.y, acc);
    acc = fmaf(e[10], w2.z, acc); acc = fmaf(e[11], w2.w, acc);
    acc = fmaf(e[12], w3.x, acc); acc = fmaf(e[13], w3.y, acc);
    acc = fmaf(e[14], w3.z, acc); acc = fmaf(e[15], w3.w, acc);
    out[b * 128 + t] = acc;
}

extern "C" void kernel_launch(void* const* d_in, const int* in_sizes, int n_in,
                              void* d_out, int out_size) {
    const float4* x4    = (const float4*)d_in[0];  // (256,128)
    const float4* Wi4   = (const float4*)d_in[1];  // (16,128)
    const float*  b_in  = (const float*)d_in[2];   // (16)
    // d_in[3] = q_weights — provably no effect on output.
    const float4* Wo4   = (const float4*)d_in[4];  // (128,16)
    const float*  b_out = (const float*)d_in[5];   // (128)
    float* out = (float*)d_out;

    quantum_layer_kernel<<<256, 128>>>(x4, Wi4, b_in, Wo4, b_out, out);
}

// round 6
// speedup vs baseline: 1.0047x; 1.0047x over previous
#include <cuda_runtime.h>

// Analytic collapse of the 16-qubit circuit (rounds 1-5):
//   theta = x @ W_in^T + b_in
//   e[b,k] = prod_{j<=k, (k-j)%4 in {0,1}} cos(theta[b,j])
//          = A_{k%4}(k) * A_{(k-1)%4}(k-1)  (residue-class prefix products)
//   out    = e @ W_out^T + b_out
// q_weights provably cannot affect the output (diagonal phases + permutations).
//
// R6 = R4 shell (128 CTAs x 256 thr: one CTA/SM, single wave, two independent
// 128-thread row-groups with named barriers) + R5 inner (xor-butterfly
// reduction, explicit SEL-free residue prefix chains, LDS.128 cs broadcast).

__global__ void __launch_bounds__(256) quantum_layer_kernel(
    const float4* __restrict__ x4,    // (256, 32) float4
    const float4* __restrict__ Wi4,   // (16, 32)  float4
    const float*  __restrict__ b_in,  // (16)
    const float4* __restrict__ Wo4,   // (128, 4)  float4
    const float*  __restrict__ b_out, // (128)
    float* __restrict__ out)          // (256, 128)
{
    __shared__ float cs[2][16];

    const int t  = threadIdx.x;
    const int g  = t >> 7;            // row-group within CTA (0/1)
    const int tt = t & 127;           // thread within group
    const int b  = (blockIdx.x << 1) + g;
    const int q  = tt >> 3;           // 16 qubits, 8 lanes each
    const int e8 = tt & 7;

    // ---- Hoist epilogue operands: latency hides under the dot phase. ----
    const float4* wo = Wo4 + tt * 4;
    const float4 w0 = wo[0], w1 = wo[1], w2 = wo[2], w3 = wo[3];
    const float  bo = b_out[tt];
    const float  bq = b_in[q];

    // ---- theta[b,q]: 8 lanes x 16 elements (4x LDG.128 each). ----
    const float4* xp = x4  + b * 32 + e8 * 4;
    const float4* wp = Wi4 + q * 32 + e8 * 4;
    float4 xa = xp[0], wa = wp[0];
    float4 xb = xp[1], wb = wp[1];
    float4 xc = xp[2], wc = wp[2];
    float4 xd = xp[3], wd = wp[3];
    float p0 = xa.x*wa.x + xa.y*wa.y + xa.z*wa.z + xa.w*wa.w;
    float p1 = xb.x*wb.x + xb.y*wb.y + xb.z*wb.z + xb.w*wb.w;
    float p2 = xc.x*wc.x + xc.y*wc.y + xc.z*wc.z + xc.w*wc.w;
    float p3 = xd.x*wd.x + xd.y*wd.y + xd.z*wd.z + xd.w*wd.w;
    float p = (p0 + p1) + (p2 + p3);
    p += __shfl_xor_sync(0xffffffffu, p, 4);
    p += __shfl_xor_sync(0xffffffffu, p, 2);
    p += __shfl_xor_sync(0xffffffffu, p, 1);
    if (e8 == 0) cs[g][q] = __cosf(p + bq);   // MUFU; |theta| small, tol 1e-3

    // Named barrier per 128-thread row-group: groups never couple.
    asm volatile("bar.sync %0, 128;" :: "r"(1 + g) : "memory");

    // ---- Per-thread residue-class prefix chains (SEL-free, depth ~5). ----
    float c[16];
    #pragma unroll
    for (int j = 0; j < 16; j += 4) {
        float4 v = *reinterpret_cast<const float4*>(&cs[g][j]);  // LDS.128 bcast
        c[j] = v.x; c[j+1] = v.y; c[j+2] = v.z; c[j+3] = v.w;
    }
    float e[16];
    float A0, A1, A2, A3;
    A0 = c[0];          e[0]  = A0;
    A1 = c[1];          e[1]  = A1 * A0;
    A2 = c[2];          e[2]  = A2 * A1;
    A3 = c[3];          e[3]  = A3 * A2;
    A0 *= c[4];         e[4]  = A0 * A3;
    A1 *= c[5];         e[5]  = A1 * A0;
    A2 *= c[6];         e[6]  = A2 * A1;
    A3 *= c[7];         e[7]  = A3 * A2;
    A0 *= c[8];         e[8]  = A0 * A3;
    A1 *= c[9];         e[9]  = A1 * A0;
    A2 *= c[10];        e[10] = A2 * A1;
    A3 *= c[11];        e[11] = A3 * A2;
    A0 *= c[12];        e[12] = A0 * A3;
    A1 *= c[13];        e[13] = A1 * A0;
    A2 *= c[14];        e[14] = A2 * A1;
    A3 *= c[15];        e[15] = A3 * A2;

    // ---- out[b,tt] = b_out[tt] + sum_k e[k] * W_out[tt,k]. ----
    float acc = bo;
    acc = fmaf(e[0],  w0.x, acc); acc = fmaf(e[1],  w0.y, acc);
    acc = fmaf(e[2],  w0.z, acc); acc = fmaf(e[3],  w0.w, acc);
    acc = fmaf(e[4],  w1.x, acc); acc = fmaf(e[5],  w1.y, acc);
    acc = fmaf(e[6],  w1.z, acc); acc = fmaf(e[7],  w1.w, acc);
    acc = fmaf(e[8],  w2.x, acc); acc = fmaf(e[9],  w2.y, acc);
    acc = fmaf(e[10], w2.z, acc); acc = fmaf(e[11], w2.w, acc);
    acc = fmaf(e[12], w3.x, acc); acc = fmaf(e[13], w3.y, acc);
    acc = fmaf(e[14], w3.z, acc); acc = fmaf(e[15], w3.w, acc);
    out[b * 128 + tt] = acc;
}

extern "C" void kernel_launch(void* const* d_in, const int* in_sizes, int n_in,
                              void* d_out, int out_size) {
    const float4* x4    = (const float4*)d_in[0];  // (256,128)
    const float4* Wi4   = (const float4*)d_in[1];  // (16,128)
    const float*  b_in  = (const float*)d_in[2];   // (16)
    // d_in[3] = q_weights — provably no effect on output.
    const float4* Wo4   = (const float4*)d_in[4];  // (128,16)
    const float*  b_out = (const float*)d_in[5];   // (128)
    float* out = (float*)d_out;

    quantum_layer_kernel<<<128, 256>>>(x4, Wi4, b_in, Wo4, b_out, out);
}

// round 7
// speedup vs baseline: 1.0385x; 1.0337x over previous
#include <cuda_runtime.h>

// Analytic collapse of the 16-qubit circuit (rounds 1-6):
//   theta = x @ W_in^T + b_in
//   e[b,k] = prod_{j<=k, (k-j)%4 in {0,1}} cos(theta[b,j])
//          = A_{k%4}(k) * A_{(k-1)%4}(k-1)  (residue-class prefix products)
//   out    = e @ W_out^T + b_out
// q_weights provably cannot affect the output (diagonal phases + permutations).
//
// R7 = R4 shell (128 CTAs x 256 thr, two independent 128-thread row-groups,
// named barriers) with (1) critical dot-phase LDGs issued FIRST (L1tex queue
// completes in issue order; epilogue loads still hide fully), (2) tree-reduced
// 16-term epilogue (depth ~28 cyc vs ~64).

__global__ void __launch_bounds__(256) quantum_layer_kernel(
    const float4* __restrict__ x4,    // (256, 32) float4
    const float4* __restrict__ Wi4,   // (16, 32)  float4
    const float*  __restrict__ b_in,  // (16)
    const float4* __restrict__ Wo4,   // (128, 4)  float4
    const float*  __restrict__ b_out, // (128)
    float* __restrict__ out)          // (256, 128)
{
    __shared__ float cs[2][16];

    const int t  = threadIdx.x;
    const int g  = t >> 7;            // row-group within CTA (0/1)
    const int tt = t & 127;           // thread within group
    const int b  = (blockIdx.x << 1) + g;
    const int q  = tt >> 3;           // 16 qubits, 8 lanes each
    const int e8 = tt & 7;

    // ---- CRITICAL loads first: they gate the barrier. ----
    const float4* xp = x4  + b * 32 + e8 * 4;
    const float4* wp = Wi4 + q * 32 + e8 * 4;
    float4 xa = xp[0], wa = wp[0];
    float4 xb = xp[1], wb = wp[1];
    float4 xc = xp[2], wc = wp[2];
    float4 xd = xp[3], wd = wp[3];
    const float bq = b_in[q];

    // ---- Non-critical epilogue operands issued after; latency hides under
    // the dot + shfl + barrier wait. ----
    const float4* wo = Wo4 + tt * 4;
    const float4 w0 = wo[0], w1 = wo[1], w2 = wo[2], w3 = wo[3];
    const float  bo = b_out[tt];

    // ---- theta[b,q]: 8 lanes x 16 elements each. ----
    float p0 = xa.x*wa.x + xa.y*wa.y + xa.z*wa.z + xa.w*wa.w;
    float p1 = xb.x*wb.x + xb.y*wb.y + xb.z*wb.z + xb.w*wb.w;
    float p2 = xc.x*wc.x + xc.y*wc.y + xc.z*wc.z + xc.w*wc.w;
    float p3 = xd.x*wd.x + xd.y*wd.y + xd.z*wd.z + xd.w*wd.w;
    float p = (p0 + p1) + (p2 + p3);
    p += __shfl_xor_sync(0xffffffffu, p, 4);
    p += __shfl_xor_sync(0xffffffffu, p, 2);
    p += __shfl_xor_sync(0xffffffffu, p, 1);
    if (e8 == 0) cs[g][q] = __cosf(p + bq);   // MUFU; |theta| small, tol 1e-3

    // Named barrier per 128-thread row-group: groups never couple.
    asm volatile("bar.sync %0, 128;" :: "r"(1 + g) : "memory");

    // ---- Per-thread residue-class prefix chains (SEL-free). ----
    float c[16];
    #pragma unroll
    for (int j = 0; j < 16; j += 4) {
        float4 v = *reinterpret_cast<const float4*>(&cs[g][j]);  // LDS.128 bcast
        c[j] = v.x; c[j+1] = v.y; c[j+2] = v.z; c[j+3] = v.w;
    }
    float e[16];
    float A0, A1, A2, A3;
    A0 = c[0];          e[0]  = A0;
    A1 = c[1];          e[1]  = A1 * A0;
    A2 = c[2];          e[2]  = A2 * A1;
    A3 = c[3];          e[3]  = A3 * A2;
    A0 *= c[4];         e[4]  = A0 * A3;
    A1 *= c[5];         e[5]  = A1 * A0;
    A2 *= c[6];         e[6]  = A2 * A1;
    A3 *= c[7];         e[7]  = A3 * A2;
    A0 *= c[8];         e[8]  = A0 * A3;
    A1 *= c[9];         e[9]  = A1 * A0;
    A2 *= c[10];        e[10] = A2 * A1;
    A3 *= c[11];        e[11] = A3 * A2;
    A0 *= c[12];        e[12] = A0 * A3;
    A1 *= c[13];        e[13] = A1 * A0;
    A2 *= c[14];        e[14] = A2 * A1;
    A3 *= c[15];        e[15] = A3 * A2;

    // ---- Tree-reduced epilogue: 4 independent partials, then combine. ----
    float s0 = bo;
    s0 = fmaf(e[0],  w0.x, s0); s0 = fmaf(e[1],  w0.y, s0);
    s0 = fmaf(e[2],  w0.z, s0); s0 = fmaf(e[3],  w0.w, s0);
    float s1 = e[4] * w1.x;
    s1 = fmaf(e[5],  w1.y, s1); s1 = fmaf(e[6],  w1.z, s1);
    s1 = fmaf(e[7],  w1.w, s1);
    float s2 = e[8] * w2.x;
    s2 = fmaf(e[9],  w2.y, s2); s2 = fmaf(e[10], w2.z, s2);
    s2 = fmaf(e[11], w2.w, s2);
    float s3 = e[12] * w3.x;
    s3 = fmaf(e[13], w3.y, s3); s3 = fmaf(e[14], w3.z, s3);
    s3 = fmaf(e[15], w3.w, s3);
    out[b * 128 + tt] = (s0 + s1) + (s2 + s3);
}

extern "C" void kernel_launch(void* const* d_in, const int* in_sizes, int n_in,
                              void* d_out, int out_size) {
    const float4* x4    = (const float4*)d_in[0];  // (256,128)
    const float4* Wi4   = (const float4*)d_in[1];  // (16,128)
    const float*  b_in  = (const float*)d_in[2];   // (16)
    // d_in[3] = q_weights — provably no effect on output.
    const float4* Wo4   = (const float4*)d_in[4];  // (128,16)
    const float*  b_out = (const float*)d_in[5];   // (128)
    float* out = (float*)d_out;

    quantum_layer_kernel<<<128, 256>>>(x4, Wi4, b_in, Wo4, b_out, out);
}